// round 1
// baseline (speedup 1.0000x reference)
#include <cuda_runtime.h>

// Problem constants (fixed by the dataset)
#define NN      50000
#define EE      1000000
#define HC      128
#define NEG     0.2f

// Capacities (expected: ~20 target in-edges, ~21 flagged nodes, ~440 edges)
#define MAXTGT   4096
#define MAXNODES 2048
#define LCAP     (1 << 18)

// ---------------- device scratch (no allocations allowed) ----------------
__device__ int      g_flagslot[NN];          // -1 = unflagged, else slot id
__device__ int      g_nodelist[MAXNODES];    // slot -> node id
__device__ int      g_tgt_src [MAXTGT];      // target's in-edge sources
__device__ int      g_tgt_eidx[MAXTGT];      // target's in-edge indices
__device__ int2     g_L[LCAP];               // (edge idx, dst slot)
__device__ float2   g_lg1[LCAP + MAXNODES];  // conv1 logits per item
__device__ unsigned g_maxkey[MAXNODES * 2];  // ordered-uint encoded max logit
__device__ float    g_sumexp[MAXNODES * 2];
__device__ float    g_msg  [MAXNODES * HC];  // unnormalized messages
__device__ float    g_xl2  [MAXNODES * HC];  // conv2 source transform
__device__ float    g_xr2t [HC];             // conv2 target transform (target)
__device__ float2   g_tl   [MAXTGT + 1];     // conv2 logits
__device__ int      g_tslot[MAXTGT + 1];
__device__ int      g_tcount, g_nnodes, g_lcount;
__device__ double   g_easum;
__device__ float    g_fill;

__device__ __forceinline__ unsigned fenc(float f) {
    unsigned u = __float_as_uint(f);
    return (u & 0x80000000u) ? ~u : (u | 0x80000000u);
}
__device__ __forceinline__ float fdec(unsigned k) {
    return __uint_as_float((k & 0x80000000u) ? (k ^ 0x80000000u) : ~k);
}
__device__ __forceinline__ float lrelu(float v) { return v > 0.f ? v : NEG * v; }

// ---------------- K0: reset scratch ----------------
__global__ void k_reset(const int* tgtp) {
    int tgt = *tgtp;
    int i = blockIdx.x * blockDim.x + threadIdx.x;
    int stride = gridDim.x * blockDim.x;
    for (int j = i; j < NN; j += stride) g_flagslot[j] = (j == tgt) ? 0 : -1;
    for (int j = i; j < MAXNODES * HC; j += stride) g_msg[j] = 0.f;
    for (int j = i; j < MAXNODES * 2; j += stride) { g_maxkey[j] = 0u; g_sumexp[j] = 0.f; }
    if (i == 0) {
        g_tcount = 0; g_nnodes = 1; g_lcount = 0; g_easum = 0.0;
        g_nodelist[0] = tgt;
    }
}

// ---------------- K1: scan edges — edge_attr mean + target in-edges + flags ----------------
__global__ void k_scan1(const int* __restrict__ src, const int* __restrict__ dst,
                        const float* __restrict__ ea, const int* tgtp, int E) {
    int tgt = *tgtp;
    int i = blockIdx.x * blockDim.x + threadIdx.x;
    int stride = gridDim.x * blockDim.x;
    double acc = 0.0;
    for (int e = i; e < E; e += stride) {
        acc += (double)ea[e];
        if (dst[e] == tgt) {
            int s = src[e];
            int idx = atomicAdd(&g_tcount, 1);
            if (idx < MAXTGT) { g_tgt_src[idx] = s; g_tgt_eidx[idx] = e; }
            int old = atomicCAS(&g_flagslot[s], -1, -2);
            if (old == -1) {
                int sl = atomicAdd(&g_nnodes, 1);
                if (sl >= MAXNODES) sl = MAXNODES - 1;
                g_nodelist[sl] = s;
                g_flagslot[s]  = sl;
            }
        }
    }
    __shared__ double sd[256];
    sd[threadIdx.x] = acc; __syncthreads();
    for (int off = blockDim.x >> 1; off; off >>= 1) {
        if (threadIdx.x < off) sd[threadIdx.x] += sd[threadIdx.x + off];
        __syncthreads();
    }
    if (threadIdx.x == 0) atomicAdd(&g_easum, sd[0]);
}

// ---------------- K2: scan edges — collect edges into flagged nodes ----------------
__global__ void k_scan2(const int* __restrict__ dst, int E) {
    int i = blockIdx.x * blockDim.x + threadIdx.x;
    if (i == 0) g_fill = (float)(g_easum / (double)EE);
    int stride = gridDim.x * blockDim.x;
    for (int e = i; e < E; e += stride) {
        int s = g_flagslot[dst[e]];
        if (s >= 0) {
            int idx = atomicAdd(&g_lcount, 1);
            if (idx < LCAP) g_L[idx] = make_int2(e, s);
        }
    }
}

// ---------------- K3: conv1 logits + segment max ----------------
__global__ void k_logit_max(const int* __restrict__ src, const int* __restrict__ dst,
                            const float* __restrict__ ea, const float* __restrict__ x,
                            const float* __restrict__ Wl1, const float* __restrict__ bl1,
                            const float* __restrict__ Wr1, const float* __restrict__ br1,
                            const float* __restrict__ We1, const float* __restrict__ att1) {
    int lc = min(g_lcount, LCAP);
    int nn = min(g_nnodes, MAXNODES);
    int total = lc + nn;
    int gid = blockIdx.x * blockDim.x + threadIdx.x;
    int stride = gridDim.x * blockDim.x;
    float fill = g_fill;
    for (int i = gid; i < total; i += stride) {
        int sn, dn, slot; float a;
        if (i < lc) {
            int2 it = g_L[i];
            slot = it.y; sn = src[it.x]; dn = dst[it.x]; a = ea[it.x];
        } else {
            slot = i - lc; sn = dn = g_nodelist[slot]; a = fill;
        }
        float xs = x[sn], xd = x[dn];
        float l0 = 0.f, l1 = 0.f;
        #pragma unroll 8
        for (int j = 0; j < HC; j++) {
            float v = fmaf(xs, Wl1[j], bl1[j]) + fmaf(xd, Wr1[j], br1[j]) + a * We1[j];
            v = lrelu(v);
            float p = v * att1[j];
            if (j < 64) l0 += p; else l1 += p;
        }
        g_lg1[i] = make_float2(l0, l1);
        atomicMax(&g_maxkey[slot * 2 + 0], fenc(l0));
        atomicMax(&g_maxkey[slot * 2 + 1], fenc(l1));
    }
}

// ---------------- K4: conv1 exp/sum + weighted message accumulation ----------------
__global__ void k_accum(const int* __restrict__ src, const float* __restrict__ x,
                        const float* __restrict__ Wl1, const float* __restrict__ bl1) {
    int lc = min(g_lcount, LCAP);
    int nn = min(g_nnodes, MAXNODES);
    int total = lc + nn;
    int gid = blockIdx.x * blockDim.x + threadIdx.x;
    int stride = gridDim.x * blockDim.x;
    for (int i = gid; i < total; i += stride) {
        int sn, slot;
        if (i < lc) { int2 it = g_L[i]; slot = it.y; sn = src[it.x]; }
        else        { slot = i - lc; sn = g_nodelist[slot]; }
        float2 lg = g_lg1[i];
        float m0 = fdec(g_maxkey[slot * 2 + 0]);
        float m1 = fdec(g_maxkey[slot * 2 + 1]);
        float e0 = expf(lg.x - m0), e1 = expf(lg.y - m1);
        atomicAdd(&g_sumexp[slot * 2 + 0], e0);
        atomicAdd(&g_sumexp[slot * 2 + 1], e1);
        float xs = x[sn];
        #pragma unroll 8
        for (int j = 0; j < HC; j++) {
            float xl = fmaf(xs, Wl1[j], bl1[j]);
            atomicAdd(&g_msg[slot * HC + j], (j < 64 ? e0 : e1) * xl);
        }
    }
}

// ---------------- K5: finalize h1 (relu) + conv2 linear transforms ----------------
__global__ void k_h1_xform(const float* __restrict__ b1,
                           const float* __restrict__ Wl2, const float* __restrict__ bl2,
                           const float* __restrict__ Wr2, const float* __restrict__ br2) {
    int nn = min(g_nnodes, MAXNODES);
    __shared__ float sh[HC];
    int j = threadIdx.x;  // blockDim = 128
    for (int s = blockIdx.x; s < nn; s += gridDim.x) {
        float denom = g_sumexp[s * 2 + (j >> 6)];
        float v = g_msg[s * HC + j] / denom + b1[j];
        sh[j] = fmaxf(v, 0.f);     // relu between layers
        __syncthreads();
        float acc = bl2[j];
        #pragma unroll 8
        for (int k = 0; k < HC; k++) acc = fmaf(sh[k], Wl2[k * HC + j], acc);
        g_xl2[s * HC + j] = acc;
        if (s == 0) {  // slot 0 == target: also compute xr2[target]
            float acc2 = br2[j];
            #pragma unroll 8
            for (int k = 0; k < HC; k++) acc2 = fmaf(sh[k], Wr2[k * HC + j], acc2);
            g_xr2t[j] = acc2;
        }
        __syncthreads();
    }
}

// ---------------- K6: conv2 attention at target + aggregate + fc ----------------
__global__ void k_conv2_fc(const float* __restrict__ eattr, const int* tgtp,
                           const float* __restrict__ We2, const float* __restrict__ att2,
                           const float* __restrict__ b2,
                           const float* __restrict__ Wfc, const float* __restrict__ bfc,
                           float* __restrict__ out) {
    int tid = threadIdx.x;  // 128 threads
    int tgt = *tgtp;
    __shared__ float xr[HC], o2[HC];
    __shared__ float ws[4];
    __shared__ float sm0, sm1, ss0, ss1;
    xr[tid] = g_xr2t[tid];
    int tc = min(g_tcount, MAXTGT);
    int items = tc + 1;  // + self-loop
    float fill = g_fill;
    __syncthreads();

    for (int i = 0; i < items; i++) {
        int jn; float a;
        if (i < tc) { jn = g_tgt_src[i]; a = eattr[g_tgt_eidx[i]]; }
        else        { jn = tgt;          a = fill; }
        int slot = g_flagslot[jn]; if (slot < 0) slot = 0;
        float v = g_xl2[slot * HC + tid] + xr[tid] + a * We2[tid];
        v = lrelu(v);
        float p = v * att2[tid];
        #pragma unroll
        for (int off = 16; off; off >>= 1) p += __shfl_down_sync(0xffffffffu, p, off);
        if ((tid & 31) == 0) ws[tid >> 5] = p;
        __syncthreads();
        if (tid == 0) {
            g_tl[i] = make_float2(ws[0] + ws[1], ws[2] + ws[3]);
            g_tslot[i] = slot;
        }
        __syncthreads();
    }

    if (tid == 0) {
        float m0 = -1e30f, m1 = -1e30f;
        for (int i = 0; i < items; i++) {
            m0 = fmaxf(m0, g_tl[i].x);
            m1 = fmaxf(m1, g_tl[i].y);
        }
        float s0 = 0.f, s1 = 0.f;
        for (int i = 0; i < items; i++) {
            s0 += expf(g_tl[i].x - m0);
            s1 += expf(g_tl[i].y - m1);
        }
        sm0 = m0; sm1 = m1; ss0 = s0; ss1 = s1;
    }
    __syncthreads();

    float acc = 0.f;
    for (int i = 0; i < items; i++) {
        float2 lg = g_tl[i];
        float alpha = (tid < 64) ? expf(lg.x - sm0) / ss0 : expf(lg.y - sm1) / ss1;
        acc += alpha * g_xl2[g_tslot[i] * HC + tid];
    }
    o2[tid] = acc + b2[tid];  // no relu after conv2
    __syncthreads();

    float r = bfc[tid];
    #pragma unroll 8
    for (int c = 0; c < HC; c++) r = fmaf(o2[c], Wfc[c * HC + tid], r);
    out[tid] = r;
}

// ---------------- launch ----------------
extern "C" void kernel_launch(void* const* d_in, const int* in_sizes, int n_in,
                              void* d_out, int out_size) {
    const float* x    = (const float*)d_in[0];
    const int*   ei   = (const int*)  d_in[1];
    const float* ea   = (const float*)d_in[2];
    const int*   tgtp = (const int*)  d_in[3];
    const float* Wl1  = (const float*)d_in[4];
    const float* bl1  = (const float*)d_in[5];
    const float* Wr1  = (const float*)d_in[6];
    const float* br1  = (const float*)d_in[7];
    const float* We1  = (const float*)d_in[8];
    const float* att1 = (const float*)d_in[9];
    const float* b1   = (const float*)d_in[10];
    const float* Wl2  = (const float*)d_in[11];
    const float* bl2  = (const float*)d_in[12];
    const float* Wr2  = (const float*)d_in[13];
    const float* br2  = (const float*)d_in[14];
    const float* We2  = (const float*)d_in[15];
    const float* att2 = (const float*)d_in[16];
    const float* b2   = (const float*)d_in[17];
    const float* Wfc  = (const float*)d_in[18];
    const float* bfc  = (const float*)d_in[19];
    float* out = (float*)d_out;

    int E = in_sizes[1] / 2;           // edge_index is (2, E)
    const int* src = ei;
    const int* dst = ei + E;

    k_reset<<<512, 256>>>(tgtp);
    k_scan1<<<1024, 256>>>(src, dst, ea, tgtp, E);
    k_scan2<<<1024, 256>>>(dst, E);
    k_logit_max<<<128, 128>>>(src, dst, ea, x, Wl1, bl1, Wr1, br1, We1, att1);
    k_accum<<<128, 128>>>(src, x, Wl1, bl1);
    k_h1_xform<<<64, 128>>>(b1, Wl2, bl2, Wr2, br2);
    k_conv2_fc<<<1, 128>>>(ea, tgtp, We2, att2, b2, Wfc, bfc, out);
    (void)n_in; (void)out_size;
}

// round 2
// speedup vs baseline: 1.7433x; 1.7433x over previous
#include <cuda_runtime.h>

#define NN       50000
#define HC       128
#define NEG      0.2f
#define MAXNODES 2048
#define MAXTGT   4096
#define LCAP     32768
#define ICAP     1024
#define TCAP     2048

// ---------------- device scratch ----------------
__device__ int    g_flagslot[NN];
__device__ int    g_nodelist[MAXNODES];
__device__ int    g_tgt_src[MAXTGT];
__device__ float  g_tgt_a[MAXTGT];
__device__ int    g_Lslot[LCAP];
__device__ float  g_Lxs[LCAP];
__device__ float  g_La[LCAP];
__device__ float  g_xl2[MAXNODES * HC];
__device__ float  g_xr2t[HC];
__device__ int    g_tcount, g_nnodes, g_lcount;
__device__ double g_easum;
__device__ float  g_fill;

__device__ __forceinline__ unsigned fenc(float f) {
    unsigned u = __float_as_uint(f);
    return (u & 0x80000000u) ? ~u : (u | 0x80000000u);
}
__device__ __forceinline__ float fdec(unsigned k) {
    return __uint_as_float((k & 0x80000000u) ? (k ^ 0x80000000u) : ~k);
}
__device__ __forceinline__ float lrelu(float v) { return v > 0.f ? v : NEG * v; }

// ---------------- K0: reset ----------------
__global__ void k_reset(const int* tgtp) {
    int tgt = *tgtp;
    int i = blockIdx.x * blockDim.x + threadIdx.x;
    int stride = gridDim.x * blockDim.x;
    int4* f4 = (int4*)g_flagslot;
    int nv = NN / 4;
    int4 m1 = make_int4(-1, -1, -1, -1);
    for (int j = i; j < nv; j += stride) f4[j] = m1;
    for (int j = nv * 4 + i; j < NN; j += stride) g_flagslot[j] = -1;
    if (i == 0) {
        g_tcount = 0; g_nnodes = 1; g_lcount = 0; g_easum = 0.0;
        g_nodelist[0] = tgt;
    }
}
// Separate tiny fixup (flag target) must come after full clear -> fold into scan1 start? No:
// do it in scan1 with an atomicCAS identical to other sources? target slot must be 0.
// Simplest: second tiny kernel is wasteful; instead have k_reset NOT clear g_flagslot[tgt]:
// handled below in k_reset2-free way: k_scan1 block0 thread0 sets it first? race.
// -> dedicated 1-thread tail inside k_reset is racy vs the clear loop across blocks.
// Use a separate 1-block kernel (cheap) fused with nothing: see k_flag below.
__global__ void k_flag(const int* tgtp) {
    if (threadIdx.x == 0) g_flagslot[*tgtp] = 0;
}

// ---------------- K1: scan edges: ea mean + target in-edges + flag sources ----------------
__global__ void k_scan1(const int* __restrict__ src, const int* __restrict__ dst,
                        const float* __restrict__ ea, const int* tgtp, int E) {
    int tgt = *tgtp;
    int i = blockIdx.x * blockDim.x + threadIdx.x;
    int stride = gridDim.x * blockDim.x;
    int nv = E >> 2;
    const int4* d4 = (const int4*)dst;
    const float4* a4 = (const float4*)ea;
    double acc = 0.0;
    for (int v = i; v < nv; v += stride) {
        int4 d = d4[v];
        float4 a = a4[v];
        acc += (double)a.x + (double)a.y + (double)a.z + (double)a.w;
        int e = v << 2;
        #pragma unroll
        for (int c = 0; c < 4; c++) {
            int dd = (c == 0) ? d.x : (c == 1) ? d.y : (c == 2) ? d.z : d.w;
            if (dd == tgt) {
                float aa = (c == 0) ? a.x : (c == 1) ? a.y : (c == 2) ? a.z : a.w;
                int idx = atomicAdd(&g_tcount, 1);
                int s = src[e + c];
                if (idx < MAXTGT) { g_tgt_src[idx] = s; g_tgt_a[idx] = aa; }
                int old = atomicCAS(&g_flagslot[s], -1, -2);
                if (old == -1) {
                    int sl = atomicAdd(&g_nnodes, 1);
                    if (sl < MAXNODES) { g_nodelist[sl] = s; g_flagslot[s] = sl; }
                }
            }
        }
    }
    for (int e = (nv << 2) + i; e < E; e += stride) {  // tail
        acc += (double)ea[e];
        if (dst[e] == tgt) {
            int idx = atomicAdd(&g_tcount, 1);
            int s = src[e];
            if (idx < MAXTGT) { g_tgt_src[idx] = s; g_tgt_a[idx] = ea[e]; }
            int old = atomicCAS(&g_flagslot[s], -1, -2);
            if (old == -1) {
                int sl = atomicAdd(&g_nnodes, 1);
                if (sl < MAXNODES) { g_nodelist[sl] = s; g_flagslot[s] = sl; }
            }
        }
    }
    __shared__ double sd[256];
    sd[threadIdx.x] = acc; __syncthreads();
    for (int off = blockDim.x >> 1; off; off >>= 1) {
        if (threadIdx.x < off) sd[threadIdx.x] += sd[threadIdx.x + off];
        __syncthreads();
    }
    if (threadIdx.x == 0) atomicAdd(&g_easum, sd[0]);
}

// ---------------- K2: collect edges into flagged nodes (also cache xs, a) --------
__global__ void k_scan2(const int* __restrict__ src, const int* __restrict__ dst,
                        const float* __restrict__ ea, const float* __restrict__ x, int E) {
    int i = blockIdx.x * blockDim.x + threadIdx.x;
    if (i == 0) g_fill = (float)(g_easum / (double)E);
    int stride = gridDim.x * blockDim.x;
    int nv = E >> 2;
    const int4* d4 = (const int4*)dst;
    for (int v = i; v < nv; v += stride) {
        int4 d = d4[v];
        int e = v << 2;
        #pragma unroll
        for (int c = 0; c < 4; c++) {
            int dd = (c == 0) ? d.x : (c == 1) ? d.y : (c == 2) ? d.z : d.w;
            int s = g_flagslot[dd];
            if (s >= 0) {
                int idx = atomicAdd(&g_lcount, 1);
                if (idx < LCAP) {
                    int sn = src[e + c];
                    g_Lslot[idx] = s;
                    g_Lxs[idx] = x[sn];
                    g_La[idx] = ea[e + c];
                }
            }
        }
    }
    for (int e = (nv << 2) + i; e < E; e += stride) {
        int s = g_flagslot[dst[e]];
        if (s >= 0) {
            int idx = atomicAdd(&g_lcount, 1);
            if (idx < LCAP) {
                g_Lslot[idx] = s; g_Lxs[idx] = x[src[e]]; g_La[idx] = ea[e];
            }
        }
    }
}

// ---------------- K3: fused conv1 per slot: softmax -> S_h -> h1 -> xl2 (and xr2t) ----
__global__ void __launch_bounds__(128) k_conv1(
        const float* __restrict__ x,
        const float* __restrict__ Wl1, const float* __restrict__ bl1,
        const float* __restrict__ Wr1, const float* __restrict__ br1,
        const float* __restrict__ We1, const float* __restrict__ att1,
        const float* __restrict__ b1,
        const float* __restrict__ Wl2, const float* __restrict__ bl2,
        const float* __restrict__ Wr2, const float* __restrict__ br2) {
    int tid = threadIdx.x, lane = tid & 31, warp = tid >> 5;
    int nn = min(g_nnodes, MAXNODES);
    int lc = min(g_lcount, LCAP);
    float fill = g_fill;

    __shared__ float swl[HC], swe[HC], satt[HC], sroff[HC], sh[HC];
    __shared__ float sxs[ICAP], sa[ICAP];
    __shared__ float2 slg[ICAP];
    __shared__ int scnt;
    __shared__ unsigned smax0, smax1;
    __shared__ float ssum[4];   // s0, s1, t0, t1

    swl[tid] = Wl1[tid]; swe[tid] = We1[tid]; satt[tid] = att1[tid];
    float wr = Wr1[tid];
    float blr = bl1[tid] + br1[tid];
    float b1c = bl1[tid] + b1[tid];

    for (int s = blockIdx.x; s < nn; s += gridDim.x) {
        int node = g_nodelist[s];
        float xd = x[node];
        if (tid == 0) {
            scnt = 1; smax0 = 0u; smax1 = 0u;
            ssum[0] = ssum[1] = ssum[2] = ssum[3] = 0.f;
            sxs[0] = xd; sa[0] = fill;          // self-loop item
        }
        sroff[tid] = fmaf(xd, wr, blr);
        __syncthreads();

        // collect this slot's items
        for (int i = tid; i < lc; i += 128) {
            if (g_Lslot[i] == s) {
                int idx = atomicAdd(&scnt, 1);
                if (idx < ICAP) { sxs[idx] = g_Lxs[i]; sa[idx] = g_La[i]; }
            }
        }
        __syncthreads();
        int cnt = min(scnt, ICAP);

        // warp-per-item logits + max
        for (int i = warp; i < cnt; i += 4) {
            float xs = sxs[i], a = sa[i];
            float p0 = 0.f, p1 = 0.f;
            #pragma unroll
            for (int k = 0; k < 4; k++) {
                int c = lane + 32 * k;
                float v = fmaf(xs, swl[c], fmaf(a, swe[c], sroff[c]));
                v = lrelu(v);
                float p = v * satt[c];
                if (k < 2) p0 += p; else p1 += p;
            }
            #pragma unroll
            for (int off = 16; off; off >>= 1) {
                p0 += __shfl_down_sync(0xffffffffu, p0, off);
                p1 += __shfl_down_sync(0xffffffffu, p1, off);
            }
            if (lane == 0) {
                slg[i] = make_float2(p0, p1);
                atomicMax(&smax0, fenc(p0));
                atomicMax(&smax1, fenc(p1));
            }
        }
        __syncthreads();
        float m0 = fdec(smax0), m1 = fdec(smax1);

        // exp sums and S_h numerators
        float a0 = 0.f, a1 = 0.f, t0 = 0.f, t1 = 0.f;
        for (int i = tid; i < cnt; i += 128) {
            float2 l = slg[i]; float xs = sxs[i];
            float e0 = expf(l.x - m0), e1 = expf(l.y - m1);
            a0 += e0; a1 += e1; t0 += e0 * xs; t1 += e1 * xs;
        }
        #pragma unroll
        for (int off = 16; off; off >>= 1) {
            a0 += __shfl_down_sync(0xffffffffu, a0, off);
            a1 += __shfl_down_sync(0xffffffffu, a1, off);
            t0 += __shfl_down_sync(0xffffffffu, t0, off);
            t1 += __shfl_down_sync(0xffffffffu, t1, off);
        }
        if (lane == 0) {
            atomicAdd(&ssum[0], a0); atomicAdd(&ssum[1], a1);
            atomicAdd(&ssum[2], t0); atomicAdd(&ssum[3], t1);
        }
        __syncthreads();
        float S = (tid < 64) ? (ssum[2] / ssum[0]) : (ssum[3] / ssum[1]);

        // h1 = relu(Wl1*S + bl1 + b1);  (sum of alpha == 1 per head)
        sh[tid] = fmaxf(fmaf(swl[tid], S, b1c), 0.f);
        __syncthreads();

        float acc = bl2[tid];
        #pragma unroll 8
        for (int k = 0; k < HC; k++) acc = fmaf(sh[k], Wl2[k * HC + tid], acc);
        g_xl2[s * HC + tid] = acc;
        if (s == 0) {
            float acc2 = br2[tid];
            #pragma unroll 8
            for (int k = 0; k < HC; k++) acc2 = fmaf(sh[k], Wr2[k * HC + tid], acc2);
            g_xr2t[tid] = acc2;
        }
        __syncthreads();
    }
}

// ---------------- K4: conv2 attention at target + aggregate + fc ----------------
__global__ void __launch_bounds__(128) k_final(
        const float* __restrict__ We2, const float* __restrict__ att2,
        const float* __restrict__ b2,
        const float* __restrict__ Wfc, const float* __restrict__ bfc,
        float* __restrict__ out) {
    int tid = threadIdx.x, lane = tid & 31, warp = tid >> 5;
    int tc = min(g_tcount, MAXTGT);
    int items = min(tc + 1, TCAP);

    __shared__ float xr[HC], swe[HC], satt[HC], o2[HC];
    __shared__ float2 slg[TCAP];
    __shared__ float salpha0[TCAP], salpha1[TCAP];
    __shared__ int sslot[TCAP];
    __shared__ unsigned smax0, smax1;
    __shared__ float ssum0, ssum1;

    xr[tid] = g_xr2t[tid]; swe[tid] = We2[tid]; satt[tid] = att2[tid];
    if (tid == 0) { smax0 = 0u; smax1 = 0u; ssum0 = 0.f; ssum1 = 0.f; }
    __syncthreads();

    // warp-per-item logits
    for (int i = warp; i < items; i += 4) {
        int slot; float a;
        if (i < tc) {
            int sn = g_tgt_src[i];
            slot = g_flagslot[sn]; if (slot < 0) slot = 0;
            a = g_tgt_a[i];
        } else { slot = 0; a = g_fill; }      // target self-loop (slot 0 == target)
        float p0 = 0.f, p1 = 0.f;
        #pragma unroll
        for (int k = 0; k < 4; k++) {
            int c = lane + 32 * k;
            float v = g_xl2[slot * HC + c] + xr[c] + a * swe[c];
            v = lrelu(v);
            float p = v * satt[c];
            if (k < 2) p0 += p; else p1 += p;
        }
        #pragma unroll
        for (int off = 16; off; off >>= 1) {
            p0 += __shfl_down_sync(0xffffffffu, p0, off);
            p1 += __shfl_down_sync(0xffffffffu, p1, off);
        }
        if (lane == 0) {
            slg[i] = make_float2(p0, p1);
            sslot[i] = slot;
            atomicMax(&smax0, fenc(p0));
            atomicMax(&smax1, fenc(p1));
        }
    }
    __syncthreads();
    float m0 = fdec(smax0), m1 = fdec(smax1);

    float a0 = 0.f, a1 = 0.f;
    for (int i = tid; i < items; i += 128) {
        float2 l = slg[i];
        float e0 = expf(l.x - m0), e1 = expf(l.y - m1);
        salpha0[i] = e0; salpha1[i] = e1;      // unnormalized
        a0 += e0; a1 += e1;
    }
    #pragma unroll
    for (int off = 16; off; off >>= 1) {
        a0 += __shfl_down_sync(0xffffffffu, a0, off);
        a1 += __shfl_down_sync(0xffffffffu, a1, off);
    }
    if (lane == 0) { atomicAdd(&ssum0, a0); atomicAdd(&ssum1, a1); }
    __syncthreads();
    float inv = (tid < 64) ? (1.f / ssum0) : (1.f / ssum1);

    float acc = 0.f;
    for (int i = 0; i < items; i++) {
        float al = ((tid < 64) ? salpha0[i] : salpha1[i]) * inv;
        acc = fmaf(al, g_xl2[sslot[i] * HC + tid], acc);
    }
    o2[tid] = acc + b2[tid];                   // no relu after conv2
    __syncthreads();

    float r = bfc[tid];
    #pragma unroll 8
    for (int k = 0; k < HC; k++) r = fmaf(o2[k], Wfc[k * HC + tid], r);
    out[tid] = r;
}

// ---------------- launch ----------------
extern "C" void kernel_launch(void* const* d_in, const int* in_sizes, int n_in,
                              void* d_out, int out_size) {
    const float* x    = (const float*)d_in[0];
    const int*   ei   = (const int*)  d_in[1];
    const float* ea   = (const float*)d_in[2];
    const int*   tgtp = (const int*)  d_in[3];
    const float* Wl1  = (const float*)d_in[4];
    const float* bl1  = (const float*)d_in[5];
    const float* Wr1  = (const float*)d_in[6];
    const float* br1  = (const float*)d_in[7];
    const float* We1  = (const float*)d_in[8];
    const float* att1 = (const float*)d_in[9];
    const float* b1   = (const float*)d_in[10];
    const float* Wl2  = (const float*)d_in[11];
    const float* bl2  = (const float*)d_in[12];
    const float* Wr2  = (const float*)d_in[13];
    const float* br2  = (const float*)d_in[14];
    const float* We2  = (const float*)d_in[15];
    const float* att2 = (const float*)d_in[16];
    const float* b2   = (const float*)d_in[17];
    const float* Wfc  = (const float*)d_in[18];
    const float* bfc  = (const float*)d_in[19];
    float* out = (float*)d_out;

    int E = in_sizes[1] / 2;
    const int* src = ei;
    const int* dst = ei + E;

    k_reset<<<128, 256>>>(tgtp);
    k_flag <<<1, 32>>>(tgtp);
    k_scan1<<<592, 256>>>(src, dst, ea, tgtp, E);
    k_scan2<<<592, 256>>>(src, dst, ea, x, E);
    k_conv1<<<64, 128>>>(x, Wl1, bl1, Wr1, br1, We1, att1, b1, Wl2, bl2, Wr2, br2);
    k_final<<<1, 128>>>(We2, att2, b2, Wfc, bfc, out);
    (void)n_in; (void)out_size;
}

// round 3
// speedup vs baseline: 1.8373x; 1.0539x over previous
#include <cuda_runtime.h>

#define NN       50000
#define HC       128
#define NEG      0.2f
#define MAXNODES 2048
#define MAXTGT   4096
#define LCAP     32768
#define ICAP     1024
#define TCAP     2048
#define BMWORDS  ((NN + 31) / 32)   // 1563

// ---------------- device scratch ----------------
__device__ unsigned g_bitmap[BMWORDS];
__device__ int    g_nodelist[MAXNODES];
__device__ int    g_tgt_src[MAXTGT];
__device__ float  g_tgt_a[MAXTGT];
__device__ int    g_Lslot[LCAP];
__device__ float  g_Lxs[LCAP];
__device__ float  g_La[LCAP];
__device__ float  g_xl2[MAXNODES * HC];
__device__ float  g_xr2t[HC];
__device__ int    g_tcount, g_nnodes, g_lcount;
__device__ double g_easum;
__device__ float  g_fill;

__device__ __forceinline__ unsigned fenc(float f) {
    unsigned u = __float_as_uint(f);
    return (u & 0x80000000u) ? ~u : (u | 0x80000000u);
}
__device__ __forceinline__ float fdec(unsigned k) {
    return __uint_as_float((k & 0x80000000u) ? (k ^ 0x80000000u) : ~k);
}
__device__ __forceinline__ float lrelu(float v) { return v > 0.f ? v : NEG * v; }

// ---------------- K0: reset (bitmap + counters only; target pre-flagged as slot 0) ----
__global__ void k_reset(const int* tgtp) {
    int tgt = *tgtp;
    int i = blockIdx.x * blockDim.x + threadIdx.x;
    int stride = gridDim.x * blockDim.x;
    int tw = tgt >> 5;
    for (int j = i; j < BMWORDS; j += stride)
        g_bitmap[j] = (j == tw) ? (1u << (tgt & 31)) : 0u;
    if (i == 0) {
        g_tcount = 0; g_nnodes = 1; g_lcount = 0; g_easum = 0.0;
        g_nodelist[0] = tgt;
    }
}

// ---------------- K1: scan edges: ea mean + target in-edges + flag sources in bitmap ----
__global__ void k_scan1(const int* __restrict__ src, const int* __restrict__ dst,
                        const float* __restrict__ ea, const int* tgtp, int E) {
    int tgt = *tgtp;
    int i = blockIdx.x * blockDim.x + threadIdx.x;
    int stride = gridDim.x * blockDim.x;
    int nv = E >> 2;
    const int4* d4 = (const int4*)dst;
    const float4* a4 = (const float4*)ea;
    double acc = 0.0;
    for (int v = i; v < nv; v += stride) {
        int4 d = d4[v];
        float4 a = a4[v];
        acc += (double)a.x + (double)a.y + (double)a.z + (double)a.w;
        int e = v << 2;
        #pragma unroll
        for (int c = 0; c < 4; c++) {
            int dd = (c == 0) ? d.x : (c == 1) ? d.y : (c == 2) ? d.z : d.w;
            if (dd == tgt) {
                float aa = (c == 0) ? a.x : (c == 1) ? a.y : (c == 2) ? a.z : a.w;
                int idx = atomicAdd(&g_tcount, 1);
                int s = src[e + c];
                if (idx < MAXTGT) { g_tgt_src[idx] = s; g_tgt_a[idx] = aa; }
                unsigned m = 1u << (s & 31);
                unsigned old = atomicOr(&g_bitmap[s >> 5], m);
                if (!(old & m)) {
                    int sl = atomicAdd(&g_nnodes, 1);
                    if (sl < MAXNODES) g_nodelist[sl] = s;
                }
            }
        }
    }
    for (int e = (nv << 2) + i; e < E; e += stride) {  // tail (E%4 != 0)
        acc += (double)ea[e];
        if (dst[e] == tgt) {
            int idx = atomicAdd(&g_tcount, 1);
            int s = src[e];
            if (idx < MAXTGT) { g_tgt_src[idx] = s; g_tgt_a[idx] = ea[e]; }
            unsigned m = 1u << (s & 31);
            unsigned old = atomicOr(&g_bitmap[s >> 5], m);
            if (!(old & m)) {
                int sl = atomicAdd(&g_nnodes, 1);
                if (sl < MAXNODES) g_nodelist[sl] = s;
            }
        }
    }
    __shared__ double sd[256];
    sd[threadIdx.x] = acc; __syncthreads();
    for (int off = blockDim.x >> 1; off; off >>= 1) {
        if (threadIdx.x < off) sd[threadIdx.x] += sd[threadIdx.x + off];
        __syncthreads();
    }
    if (threadIdx.x == 0) atomicAdd(&g_easum, sd[0]);
}

// ---------------- K2: collect edges into flagged nodes (shared bitmap + nodelist) ----
__global__ void k_scan2(const int* __restrict__ src, const int* __restrict__ dst,
                        const float* __restrict__ ea, const float* __restrict__ x, int E) {
    __shared__ unsigned sbm[BMWORDS];
    __shared__ int snl[MAXNODES];
    __shared__ int snn;
    int tid = threadIdx.x;
    int i = blockIdx.x * blockDim.x + tid;
    if (i == 0) g_fill = (float)(g_easum / (double)E);
    int stride = gridDim.x * blockDim.x;

    for (int j = tid; j < BMWORDS; j += blockDim.x) sbm[j] = g_bitmap[j];
    if (tid == 0) snn = min(g_nnodes, MAXNODES);
    __syncthreads();
    int nn = snn;
    for (int j = tid; j < nn; j += blockDim.x) snl[j] = g_nodelist[j];
    __syncthreads();

    int nv = E >> 2;
    const int4* d4 = (const int4*)dst;
    for (int v = i; v < nv; v += stride) {
        int4 d = d4[v];
        int e = v << 2;
        #pragma unroll
        for (int c = 0; c < 4; c++) {
            int dd = (c == 0) ? d.x : (c == 1) ? d.y : (c == 2) ? d.z : d.w;
            if ((sbm[dd >> 5] >> (dd & 31)) & 1u) {
                int slot = 0;
                for (int t = 0; t < nn; t++) { if (snl[t] == dd) { slot = t; break; } }
                int idx = atomicAdd(&g_lcount, 1);
                if (idx < LCAP) {
                    g_Lslot[idx] = slot;
                    g_Lxs[idx]   = x[src[e + c]];
                    g_La[idx]    = ea[e + c];
                }
            }
        }
    }
    for (int e = (nv << 2) + i; e < E; e += stride) {
        int dd = dst[e];
        if ((sbm[dd >> 5] >> (dd & 31)) & 1u) {
            int slot = 0;
            for (int t = 0; t < nn; t++) { if (snl[t] == dd) { slot = t; break; } }
            int idx = atomicAdd(&g_lcount, 1);
            if (idx < LCAP) {
                g_Lslot[idx] = slot; g_Lxs[idx] = x[src[e]]; g_La[idx] = ea[e];
            }
        }
    }
}

// ---------------- K3: fused conv1 per slot: softmax -> S_h -> h1 -> xl2 (and xr2t) ----
__global__ void __launch_bounds__(128) k_conv1(
        const float* __restrict__ x,
        const float* __restrict__ Wl1, const float* __restrict__ bl1,
        const float* __restrict__ Wr1, const float* __restrict__ br1,
        const float* __restrict__ We1, const float* __restrict__ att1,
        const float* __restrict__ b1,
        const float* __restrict__ Wl2, const float* __restrict__ bl2,
        const float* __restrict__ Wr2, const float* __restrict__ br2) {
    int tid = threadIdx.x, lane = tid & 31, warp = tid >> 5;
    int nn = min(g_nnodes, MAXNODES);
    int lc = min(g_lcount, LCAP);
    float fill = g_fill;

    __shared__ float swl[HC], swe[HC], satt[HC], sroff[HC], sh[HC];
    __shared__ float sxs[ICAP], sa[ICAP];
    __shared__ float2 slg[ICAP];
    __shared__ int scnt;
    __shared__ unsigned smax0, smax1;
    __shared__ float ssum[4];

    swl[tid] = Wl1[tid]; swe[tid] = We1[tid]; satt[tid] = att1[tid];
    float wr = Wr1[tid];
    float blr = bl1[tid] + br1[tid];
    float b1c = bl1[tid] + b1[tid];

    for (int s = blockIdx.x; s < nn; s += gridDim.x) {
        int node = g_nodelist[s];
        float xd = x[node];
        if (tid == 0) {
            scnt = 1; smax0 = 0u; smax1 = 0u;
            ssum[0] = ssum[1] = ssum[2] = ssum[3] = 0.f;
            sxs[0] = xd; sa[0] = fill;          // self-loop item
        }
        sroff[tid] = fmaf(xd, wr, blr);
        __syncthreads();

        for (int i = tid; i < lc; i += 128) {
            if (g_Lslot[i] == s) {
                int idx = atomicAdd(&scnt, 1);
                if (idx < ICAP) { sxs[idx] = g_Lxs[i]; sa[idx] = g_La[i]; }
            }
        }
        __syncthreads();
        int cnt = min(scnt, ICAP);

        for (int i = warp; i < cnt; i += 4) {
            float xs = sxs[i], a = sa[i];
            float p0 = 0.f, p1 = 0.f;
            #pragma unroll
            for (int k = 0; k < 4; k++) {
                int c = lane + 32 * k;
                float v = fmaf(xs, swl[c], fmaf(a, swe[c], sroff[c]));
                v = lrelu(v);
                float p = v * satt[c];
                if (k < 2) p0 += p; else p1 += p;
            }
            #pragma unroll
            for (int off = 16; off; off >>= 1) {
                p0 += __shfl_down_sync(0xffffffffu, p0, off);
                p1 += __shfl_down_sync(0xffffffffu, p1, off);
            }
            if (lane == 0) {
                slg[i] = make_float2(p0, p1);
                atomicMax(&smax0, fenc(p0));
                atomicMax(&smax1, fenc(p1));
            }
        }
        __syncthreads();
        float m0 = fdec(smax0), m1 = fdec(smax1);

        float a0 = 0.f, a1 = 0.f, t0 = 0.f, t1 = 0.f;
        for (int i = tid; i < cnt; i += 128) {
            float2 l = slg[i]; float xs = sxs[i];
            float e0 = expf(l.x - m0), e1 = expf(l.y - m1);
            a0 += e0; a1 += e1; t0 += e0 * xs; t1 += e1 * xs;
        }
        #pragma unroll
        for (int off = 16; off; off >>= 1) {
            a0 += __shfl_down_sync(0xffffffffu, a0, off);
            a1 += __shfl_down_sync(0xffffffffu, a1, off);
            t0 += __shfl_down_sync(0xffffffffu, t0, off);
            t1 += __shfl_down_sync(0xffffffffu, t1, off);
        }
        if (lane == 0) {
            atomicAdd(&ssum[0], a0); atomicAdd(&ssum[1], a1);
            atomicAdd(&ssum[2], t0); atomicAdd(&ssum[3], t1);
        }
        __syncthreads();
        float S = (tid < 64) ? (ssum[2] / ssum[0]) : (ssum[3] / ssum[1]);

        sh[tid] = fmaxf(fmaf(swl[tid], S, b1c), 0.f);   // h1 = relu(Wl1*S + bl1 + b1)
        __syncthreads();

        float acc = bl2[tid];
        #pragma unroll 8
        for (int k = 0; k < HC; k++) acc = fmaf(sh[k], Wl2[k * HC + tid], acc);
        g_xl2[s * HC + tid] = acc;
        if (s == 0) {
            float acc2 = br2[tid];
            #pragma unroll 8
            for (int k = 0; k < HC; k++) acc2 = fmaf(sh[k], Wr2[k * HC + tid], acc2);
            g_xr2t[tid] = acc2;
        }
        __syncthreads();
    }
}

// ---------------- K4: conv2 attention at target + aggregate + fc ----------------
__global__ void __launch_bounds__(128) k_final(
        const float* __restrict__ We2, const float* __restrict__ att2,
        const float* __restrict__ b2,
        const float* __restrict__ Wfc, const float* __restrict__ bfc,
        float* __restrict__ out) {
    int tid = threadIdx.x, lane = tid & 31, warp = tid >> 5;
    int tc = min(g_tcount, MAXTGT);
    int items = min(tc + 1, TCAP);
    int nn = min(g_nnodes, MAXNODES);

    __shared__ float xr[HC], swe[HC], satt[HC], o2[HC];
    __shared__ int snl[MAXNODES];
    __shared__ float2 slg[TCAP];
    __shared__ float salpha0[TCAP], salpha1[TCAP];
    __shared__ int sslot[TCAP];
    __shared__ unsigned smax0, smax1;
    __shared__ float ssum0, ssum1;

    xr[tid] = g_xr2t[tid]; swe[tid] = We2[tid]; satt[tid] = att2[tid];
    if (tid == 0) { smax0 = 0u; smax1 = 0u; ssum0 = 0.f; ssum1 = 0.f; }
    for (int j = tid; j < nn; j += 128) snl[j] = g_nodelist[j];
    __syncthreads();

    for (int i = warp; i < items; i += 4) {
        int slot = 0; float a;
        if (i < tc) {
            int sn = g_tgt_src[i];
            for (int t = 0; t < nn; t++) { if (snl[t] == sn) { slot = t; break; } }
            a = g_tgt_a[i];
        } else { slot = 0; a = g_fill; }      // target self-loop (slot 0 == target)
        float p0 = 0.f, p1 = 0.f;
        #pragma unroll
        for (int k = 0; k < 4; k++) {
            int c = lane + 32 * k;
            float v = g_xl2[slot * HC + c] + xr[c] + a * swe[c];
            v = lrelu(v);
            float p = v * satt[c];
            if (k < 2) p0 += p; else p1 += p;
        }
        #pragma unroll
        for (int off = 16; off; off >>= 1) {
            p0 += __shfl_down_sync(0xffffffffu, p0, off);
            p1 += __shfl_down_sync(0xffffffffu, p1, off);
        }
        if (lane == 0) {
            slg[i] = make_float2(p0, p1);
            sslot[i] = slot;
            atomicMax(&smax0, fenc(p0));
            atomicMax(&smax1, fenc(p1));
        }
    }
    __syncthreads();
    float m0 = fdec(smax0), m1 = fdec(smax1);

    float a0 = 0.f, a1 = 0.f;
    for (int i = tid; i < items; i += 128) {
        float2 l = slg[i];
        float e0 = expf(l.x - m0), e1 = expf(l.y - m1);
        salpha0[i] = e0; salpha1[i] = e1;
        a0 += e0; a1 += e1;
    }
    #pragma unroll
    for (int off = 16; off; off >>= 1) {
        a0 += __shfl_down_sync(0xffffffffu, a0, off);
        a1 += __shfl_down_sync(0xffffffffu, a1, off);
    }
    if (lane == 0) { atomicAdd(&ssum0, a0); atomicAdd(&ssum1, a1); }
    __syncthreads();
    float inv = (tid < 64) ? (1.f / ssum0) : (1.f / ssum1);

    float acc = 0.f;
    for (int i = 0; i < items; i++) {
        float al = ((tid < 64) ? salpha0[i] : salpha1[i]) * inv;
        acc = fmaf(al, g_xl2[sslot[i] * HC + tid], acc);
    }
    o2[tid] = acc + b2[tid];                   // no relu after conv2
    __syncthreads();

    float r = bfc[tid];
    #pragma unroll 8
    for (int k = 0; k < HC; k++) r = fmaf(o2[k], Wfc[k * HC + tid], r);
    out[tid] = r;
}

// ---------------- launch ----------------
extern "C" void kernel_launch(void* const* d_in, const int* in_sizes, int n_in,
                              void* d_out, int out_size) {
    const float* x    = (const float*)d_in[0];
    const int*   ei   = (const int*)  d_in[1];
    const float* ea   = (const float*)d_in[2];
    const int*   tgtp = (const int*)  d_in[3];
    const float* Wl1  = (const float*)d_in[4];
    const float* bl1  = (const float*)d_in[5];
    const float* Wr1  = (const float*)d_in[6];
    const float* br1  = (const float*)d_in[7];
    const float* We1  = (const float*)d_in[8];
    const float* att1 = (const float*)d_in[9];
    const float* b1   = (const float*)d_in[10];
    const float* Wl2  = (const float*)d_in[11];
    const float* bl2  = (const float*)d_in[12];
    const float* Wr2  = (const float*)d_in[13];
    const float* br2  = (const float*)d_in[14];
    const float* We2  = (const float*)d_in[15];
    const float* att2 = (const float*)d_in[16];
    const float* b2   = (const float*)d_in[17];
    const float* Wfc  = (const float*)d_in[18];
    const float* bfc  = (const float*)d_in[19];
    float* out = (float*)d_out;

    int E = in_sizes[1] / 2;
    const int* src = ei;
    const int* dst = ei + E;

    k_reset<<<8, 256>>>(tgtp);
    k_scan1<<<592, 256>>>(src, dst, ea, tgtp, E);
    k_scan2<<<592, 256>>>(src, dst, ea, x, E);
    k_conv1<<<64, 128>>>(x, Wl1, bl1, Wr1, br1, We1, att1, b1, Wl2, bl2, Wr2, br2);
    k_final<<<1, 128>>>(We2, att2, b2, Wfc, bfc, out);
    (void)n_in; (void)out_size;
}